// round 3
// baseline (speedup 1.0000x reference)
#include <cuda_runtime.h>
#include <cstdint>

// QuantumCircuitSimulator2: 24 qubits, 8 steps of 4-qubit (16x16 complex) gates.
// Fused 2 steps per kernel via SMEM tiling:
//   tile = 12 varying bits = union(targetsA, targetsB) + lowest non-union bits.
//   SMEM layout: gate-A targets at slots 8..11 (stride-256 conflict-free gather),
//   B-only targets at slots 7..down, rest ascending from slot 0. Skewed by (s>>8).

#define NQ 24
#define NSTATE (1u << NQ)
#define NSTEPS 8
#define TILE_BITS 12
#define TILE (1u << TILE_BITS)          // 4096 amplitudes per block
#define NBLOCKS (1u << (NQ - TILE_BITS))  // 4096 blocks
#define PLANE (TILE + 15)               // skewed plane size (max addr 4095+15)

#define SADDR(s) ((s) + ((s) >> 8))

// ---- packed f32x2 helpers (Blackwell FFMA2 path) ----
__device__ __forceinline__ unsigned long long fma2(unsigned long long a,
                                                   unsigned long long b,
                                                   unsigned long long c) {
    unsigned long long d;
    asm("fma.rn.f32x2 %0, %1, %2, %3;" : "=l"(d) : "l"(a), "l"(b), "l"(c));
    return d;
}
__device__ __forceinline__ unsigned long long pack2(float lo, float hi) {
    unsigned long long d;
    asm("mov.b64 %0, {%1, %2};" : "=l"(d) : "f"(lo), "f"(hi));
    return d;
}
__device__ __forceinline__ void unpack2(unsigned long long v, float& lo, float& hi) {
    asm("mov.b64 {%0, %1}, %2;" : "=f"(lo), "=f"(hi) : "l"(v));
}

// Apply one 16x16 complex gate (Karatsuba tables in sG: A=gr, B=gr+gi, C=gi-gr)
// to the group owned by this thread. Slots: s = base | combo(bm0..bm3),
// bmX = SMEM-slot mask of gate target bit X. Reads+writes only own 16 slots.
__device__ __forceinline__ void apply_gate(float* __restrict__ Re,
                                           float* __restrict__ Im,
                                           const float* __restrict__ sG,
                                           unsigned base, unsigned bm0,
                                           unsigned bm1, unsigned bm2,
                                           unsigned bm3) {
    float sr[16], si[16];
    unsigned ad[16];
#pragma unroll
    for (int k = 0; k < 16; k++) {
        unsigned s = base | ((k & 1) ? bm0 : 0u) | ((k & 2) ? bm1 : 0u) |
                     ((k & 4) ? bm2 : 0u) | ((k & 8) ? bm3 : 0u);
        unsigned a = SADDR(s);
        ad[k] = a;
        sr[k] = Re[a];
        si[k] = Im[a];
    }

    unsigned long long sr2[8], si2[8], u2[8];
#pragma unroll
    for (int kk = 0; kk < 8; kk++) {
        sr2[kk] = pack2(sr[2 * kk], sr[2 * kk + 1]);
        si2[kk] = pack2(si[2 * kk], si[2 * kk + 1]);
        u2[kk]  = pack2(sr[2 * kk] + si[2 * kk], sr[2 * kk + 1] + si[2 * kk + 1]);
    }

    float outR[16], outI[16];
#pragma unroll
    for (int j = 0; j < 16; j++) {
        const unsigned long long* Aj =
            reinterpret_cast<const unsigned long long*>(sG + j * 16);
        const unsigned long long* Bj =
            reinterpret_cast<const unsigned long long*>(sG + 256 + j * 16);
        const unsigned long long* Cj =
            reinterpret_cast<const unsigned long long*>(sG + 512 + j * 16);
        unsigned long long a1 = 0ull, a2 = 0ull, a3 = 0ull;
#pragma unroll
        for (int kk = 0; kk < 8; kk++) {
            a1 = fma2(Aj[kk], u2[kk], a1);   // gr*(sr+si)
            a2 = fma2(Bj[kk], si2[kk], a2);  // (gr+gi)*si
            a3 = fma2(Cj[kk], sr2[kk], a3);  // (gi-gr)*sr
        }
        float lo, hi, t1, t2, t3;
        unpack2(a1, lo, hi); t1 = lo + hi;
        unpack2(a2, lo, hi); t2 = lo + hi;
        unpack2(a3, lo, hi); t3 = lo + hi;
        outR[j] = t1 - t2;   // re = gr*sr - gi*si
        outI[j] = t1 + t3;   // im = gr*si + gi*sr
    }
#pragma unroll
    for (int j = 0; j < 16; j++) {
        Re[ad[j]] = outR[j];
        Im[ad[j]] = outI[j];
    }
}

__global__ __launch_bounds__(256, 2)
void qstep2_kernel(const float* __restrict__ src,
                   float* __restrict__ dst,
                   const float* __restrict__ gates,
                   const int* __restrict__ targets_raw,
                   int stepA, int stepB) {
    __shared__ __align__(16) float smemRe[PLANE];
    __shared__ __align__(16) float smemIm[PLANE];
    __shared__ __align__(16) float sGA[768];
    __shared__ __align__(16) float sGB[768];
    __shared__ int pArr[12];      // sorted physical bits of V
    __shared__ int slotArr[12];   // SMEM slot of sorted bit j
    __shared__ int bMaskS[4];     // slot masks of gate-B targets (gate order)
    __shared__ int nbArr[8];      // non-B slots, ascending
    __shared__ unsigned uVmask;

    const int tid = threadIdx.x;

    // ---- Karatsuba gate tables for both steps ----
    {
        const float* gA = gates + (size_t)stepA * 512;
        const float* gB = gates + (size_t)stepB * 512;
        for (int i = tid; i < 768; i += 256) {
            int t = i >> 8;
            int idx = i & 255;
            float gr = gA[idx], gi = gA[256 + idx];
            sGA[i] = (t == 0) ? gr : ((t == 1) ? (gr + gi) : (gi - gr));
            gr = gB[idx]; gi = gB[256 + idx];
            sGB[i] = (t == 0) ? gr : ((t == 1) ? (gr + gi) : (gi - gr));
        }
    }

    // ---- per-block setup (thread 0) ----
    if (tid == 0) {
        // dtype detect: int64 targets have zero odd words (values < 24)
        int stride = (targets_raw[1] == 0 && targets_raw[3] == 0) ? 2 : 1;
        int qA[4], qB[4];
#pragma unroll
        for (int t = 0; t < 4; t++) {
            qA[t] = targets_raw[(stepA * 4 + t) * stride];
            qB[t] = targets_raw[(stepB * 4 + t) * stride];
        }
        unsigned Am = 0, Bm = 0;
#pragma unroll
        for (int t = 0; t < 4; t++) { Am |= 1u << qA[t]; Bm |= 1u << qB[t]; }
        unsigned U = Am | Bm;
        unsigned V = U;
        int need = TILE_BITS - __popc(U);
        for (int b = 0; need > 0; b++)
            if (!((V >> b) & 1u)) { V |= 1u << b; need--; }
        uVmask = V;

        int slot_of[24];
#pragma unroll
        for (int t = 0; t < 4; t++) slot_of[qA[t]] = 8 + t;  // A targets: slots 8..11
        int hi = 7;
#pragma unroll
        for (int t = 0; t < 4; t++)
            if (!((Am >> qB[t]) & 1u)) slot_of[qB[t]] = hi--;  // B-only: high slots
        int lo = 0;
        for (int b = 0; b < 24; b++)
            if (((V >> b) & 1u) && !((U >> b) & 1u)) slot_of[b] = lo++;  // rest

        int j = 0;
        for (int b = 0; b < 24; b++)
            if ((V >> b) & 1u) { pArr[j] = b; slotArr[j] = slot_of[b]; j++; }

        bool isB[12];
#pragma unroll
        for (int s = 0; s < 12; s++) isB[s] = false;
#pragma unroll
        for (int t = 0; t < 4; t++) {
            bMaskS[t] = 1 << slot_of[qB[t]];
            isB[slot_of[qB[t]]] = true;
        }
        j = 0;
        for (int s = 0; s < 12; s++)
            if (!isB[s]) nbArr[j++] = s;
    }
    __syncthreads();

    // ---- per-thread copy mappings ----
    unsigned V = uVmask;
    unsigned outer = 0;
    {
        unsigned ob = blockIdx.x;
        for (int b = 0; b < 24; b++)
            if (!((V >> b) & 1u)) { outer |= (ob & 1u) << b; ob >>= 1; }
    }
    unsigned sLo = 0, gLo = 0;
#pragma unroll
    for (int j = 0; j < 8; j++)
        if ((tid >> j) & 1) { gLo |= 1u << pArr[j]; sLo |= 1u << slotArr[j]; }

    unsigned sB = 0;
#pragma unroll
    for (int j = 0; j < 8; j++)
        if ((tid >> j) & 1) sB |= 1u << nbArr[j];

    const float* __restrict__ srcRe = src;
    const float* __restrict__ srcIm = src + NSTATE;
    float* __restrict__ dstRe = dst;
    float* __restrict__ dstIm = dst + NSTATE;

    // ---- copy-in (coalesced global -> permuted SMEM) ----
#pragma unroll
    for (int cc = 0; cc < 16; cc++) {
        unsigned gHi = 0, sHi = 0;
#pragma unroll
        for (int jj = 0; jj < 4; jj++)
            if ((cc >> jj) & 1) {
                gHi |= 1u << pArr[8 + jj];
                sHi |= 1u << slotArr[8 + jj];
            }
        unsigned g = outer + gHi + gLo;
        unsigned a = SADDR(sHi + sLo);
        smemRe[a] = srcRe[g];
        smemIm[a] = srcIm[g];
    }
    __syncthreads();

    // ---- gate A: targets at slots 8..11 (gate order) ----
    apply_gate(smemRe, smemIm, sGA, (unsigned)tid, 256u, 512u, 1024u, 2048u);
    __syncthreads();

    // ---- gate B: targets at bMaskS slots, groups over nbArr slots ----
    apply_gate(smemRe, smemIm, sGB, sB,
               (unsigned)bMaskS[0], (unsigned)bMaskS[1],
               (unsigned)bMaskS[2], (unsigned)bMaskS[3]);
    __syncthreads();

    // ---- copy-out (permuted SMEM -> coalesced global) ----
#pragma unroll
    for (int cc = 0; cc < 16; cc++) {
        unsigned gHi = 0, sHi = 0;
#pragma unroll
        for (int jj = 0; jj < 4; jj++)
            if ((cc >> jj) & 1) {
                gHi |= 1u << pArr[8 + jj];
                sHi |= 1u << slotArr[8 + jj];
            }
        unsigned g = outer + gHi + gLo;
        unsigned a = SADDR(sHi + sLo);
        dstRe[g] = smemRe[a];
        dstIm[g] = smemIm[a];
    }
}

extern "C" void kernel_launch(void* const* d_in, const int* in_sizes, int n_in,
                              void* d_out, int out_size) {
    const float* state   = (const float*)d_in[0];
    const int*   targets = (const int*)d_in[1];
    const float* gates   = (const float*)d_in[2];
    float*       out     = (float*)d_out;

    dim3 block(256);
    dim3 grid(NBLOCKS);  // 4096 blocks, each owns a disjoint 4096-amplitude tile

    // 4 fused kernels; steps (0,1),(2,3),(4,5),(6,7). In-place after first
    // (blocks own disjoint tiles -> race-free).
    qstep2_kernel<<<grid, block>>>(state, out, gates, targets, 0, 1);
    qstep2_kernel<<<grid, block>>>(out, out, gates, targets, 2, 3);
    qstep2_kernel<<<grid, block>>>(out, out, gates, targets, 4, 5);
    qstep2_kernel<<<grid, block>>>(out, out, gates, targets, 6, 7);
}

// round 4
// speedup vs baseline: 1.1156x; 1.1156x over previous
#include <cuda_runtime.h>
#include <cstdint>

// QuantumCircuitSimulator2: 24 qubits, 8 steps of 4-qubit (16x16 complex) gates.
// Fuse 3 steps per kernel (union of targets <= 12 = tile bits).
// SMEM tile: 4096 complex (float2), skewed a = s + (s>>4) for conflict-free gathers.
// Slot layout: gate-A targets at slots 8..11, B-only at 7.., C-only next, free low.

#define NQ 24
#define NSTATE (1u << NQ)
#define TILE_BITS 12
#define TILE (1u << TILE_BITS)
#define NBLOCKS (1u << (NQ - TILE_BITS))
#define PLANE (TILE + (TILE >> 4))     // 4352 float2

#define SADDR2(s) ((s) + ((s) >> 4))

__device__ __forceinline__ unsigned long long fma2(unsigned long long a,
                                                   unsigned long long b,
                                                   unsigned long long c) {
    unsigned long long d;
    asm("fma.rn.f32x2 %0, %1, %2, %3;" : "=l"(d) : "l"(a), "l"(b), "l"(c));
    return d;
}
__device__ __forceinline__ unsigned long long pack2(float lo, float hi) {
    unsigned long long d;
    asm("mov.b64 %0, {%1, %2};" : "=l"(d) : "f"(lo), "f"(hi));
    return d;
}
__device__ __forceinline__ void unpack2(unsigned long long v, float& lo, float& hi) {
    asm("mov.b64 {%0, %1}, %2;" : "=f"(lo), "=f"(hi) : "l"(v));
}

// One 16x16 complex gate on this thread's group. Karatsuba tables in sG:
// rows j: A=gr, B=gr+gi, C=gi-gr. Reads 16 slots, packs, then computes+stores
// inline per output (minimal live registers).
__device__ __forceinline__ void apply_gate(float2* __restrict__ S,
                                           const float* __restrict__ sG,
                                           unsigned base, unsigned bm0,
                                           unsigned bm1, unsigned bm2,
                                           unsigned bm3) {
    unsigned long long sr2[8], si2[8], u2[8];
#pragma unroll
    for (int kk = 0; kk < 8; kk++) {
        unsigned s0 = base | ((kk & 1) ? bm1 : 0u) | ((kk & 2) ? bm2 : 0u) |
                      ((kk & 4) ? bm3 : 0u);
        unsigned s1 = s0 | bm0;
        float2 c0 = S[SADDR2(s0)];
        float2 c1 = S[SADDR2(s1)];
        sr2[kk] = pack2(c0.x, c1.x);
        si2[kk] = pack2(c0.y, c1.y);
        u2[kk]  = pack2(c0.x + c0.y, c1.x + c1.y);
    }
#pragma unroll
    for (int j = 0; j < 16; j++) {
        const unsigned long long* Aj =
            reinterpret_cast<const unsigned long long*>(sG + j * 16);
        const unsigned long long* Bj =
            reinterpret_cast<const unsigned long long*>(sG + 256 + j * 16);
        const unsigned long long* Cj =
            reinterpret_cast<const unsigned long long*>(sG + 512 + j * 16);
        unsigned long long a1 = 0ull, a2 = 0ull, a3 = 0ull;
#pragma unroll
        for (int kk = 0; kk < 8; kk++) {
            a1 = fma2(Aj[kk], u2[kk], a1);   // gr*(sr+si)
            a2 = fma2(Bj[kk], si2[kk], a2);  // (gr+gi)*si
            a3 = fma2(Cj[kk], sr2[kk], a3);  // (gi-gr)*sr
        }
        float lo, hi;
        unpack2(a1, lo, hi); float t1 = lo + hi;
        unpack2(a2, lo, hi); float t2 = lo + hi;
        unpack2(a3, lo, hi); float t3 = lo + hi;
        unsigned sj = base | ((j & 1) ? bm0 : 0u) | ((j & 2) ? bm1 : 0u) |
                      ((j & 4) ? bm2 : 0u) | ((j & 8) ? bm3 : 0u);
        S[SADDR2(sj)] = make_float2(t1 - t2, t1 + t3);
    }
}

__global__ __launch_bounds__(256, 3)
void qstep3_kernel(const float* __restrict__ src,
                   float* __restrict__ dst,
                   const float* __restrict__ gates,
                   const int* __restrict__ targets_raw,
                   int stepA, int stepB, int stepC) {
    __shared__ __align__(16) float2 S[PLANE];
    __shared__ __align__(16) float sG[3][768];
    __shared__ int pArr[12];        // physical bits of V (ascending)
    __shared__ int slotArr[12];     // SMEM slot of bit pArr[j]
    __shared__ int bMask[2][4];     // slot masks: gate B, gate C targets
    __shared__ int nbArr[2][8];     // non-target slots (ascending): B, C
    __shared__ unsigned uVmask;

    const int tid = threadIdx.x;
    const int ngates = (stepC >= 0) ? 3 : 2;

    // ---- Karatsuba gate tables ----
    {
        int steps[3] = {stepA, stepB, stepC};
        for (int g = 0; g < ngates; g++) {
            const float* gp = gates + (size_t)steps[g] * 512;
            for (int i = tid; i < 768; i += 256) {
                int t = i >> 8;
                int idx = i & 255;
                float gr = gp[idx], gi = gp[256 + idx];
                sG[g][i] = (t == 0) ? gr : ((t == 1) ? (gr + gi) : (gi - gr));
            }
        }
    }

    // ---- per-block setup ----
    if (tid == 0) {
        int stride = (targets_raw[1] == 0 && targets_raw[3] == 0) ? 2 : 1;
        int steps[3] = {stepA, stepB, stepC};
        int q[3][4];
        for (int g = 0; g < ngates; g++)
            for (int t = 0; t < 4; t++)
                q[g][t] = targets_raw[(steps[g] * 4 + t) * stride];

        unsigned U = 0;
        for (int g = 0; g < ngates; g++)
            for (int t = 0; t < 4; t++) U |= 1u << q[g][t];
        unsigned V = U;
        int need = TILE_BITS - __popc(U);
        for (int b = 0; need > 0; b++)
            if (!((V >> b) & 1u)) { V |= 1u << b; need--; }
        uVmask = V;

        int slot_of[24];
        for (int b = 0; b < 24; b++) slot_of[b] = -1;
        for (int t = 0; t < 4; t++) slot_of[q[0][t]] = 8 + t;  // A: slots 8..11
        int hi = 7;
        for (int g = 1; g < ngates; g++)
            for (int t = 0; t < 4; t++)
                if (slot_of[q[g][t]] < 0) slot_of[q[g][t]] = hi--;
        int fs = 0;
        for (int b = 0; b < 24; b++)
            if (((V >> b) & 1u) && slot_of[b] < 0) slot_of[b] = fs++;

        int j = 0;
        for (int b = 0; b < 24; b++)
            if ((V >> b) & 1u) { pArr[j] = b; slotArr[j] = slot_of[b]; j++; }

        for (int g = 1; g < ngates; g++) {
            unsigned tm = 0;
            for (int t = 0; t < 4; t++) {
                bMask[g - 1][t] = 1 << slot_of[q[g][t]];
                tm |= 1u << slot_of[q[g][t]];
            }
            int jj = 0;
            for (int s3 = 0; s3 < 12; s3++)
                if (!((tm >> s3) & 1u)) nbArr[g - 1][jj++] = s3;
        }
    }
    __syncthreads();

    // ---- per-thread mappings ----
    const unsigned V = uVmask;
    unsigned outer = 0;
    {
        unsigned ob = blockIdx.x;
        for (int b = 0; b < 24; b++)
            if (!((V >> b) & 1u)) { outer |= (ob & 1u) << b; ob >>= 1; }
    }
    unsigned gLo = 0, sLo = 0;
#pragma unroll
    for (int j = 0; j < 8; j++)
        if ((tid >> j) & 1) { gLo |= 1u << pArr[j]; sLo |= 1u << slotArr[j]; }

    const float* __restrict__ srcRe = src;
    const float* __restrict__ srcIm = src + NSTATE;

    // ---- copy-in: coalesced global -> permuted SMEM (float2) ----
#pragma unroll
    for (int cc = 0; cc < 16; cc++) {
        unsigned gHi = 0, sHi = 0;
#pragma unroll
        for (int jj = 0; jj < 4; jj++)
            if ((cc >> jj) & 1) {
                gHi |= 1u << pArr[8 + jj];
                sHi |= 1u << slotArr[8 + jj];
            }
        unsigned g = outer + gHi + gLo;
        S[SADDR2(sHi + sLo)] = make_float2(srcRe[g], srcIm[g]);
    }
    __syncthreads();

    // ---- gate A: targets at slots 8..11 (gate-order), base = tid ----
    apply_gate(S, sG[0], (unsigned)tid, 256u, 512u, 1024u, 2048u);
    __syncthreads();

    // ---- gate B ----
    {
        unsigned baseB = 0;
#pragma unroll
        for (int j = 0; j < 8; j++)
            if ((tid >> j) & 1) baseB |= 1u << nbArr[0][j];
        apply_gate(S, sG[1], baseB, (unsigned)bMask[0][0], (unsigned)bMask[0][1],
                   (unsigned)bMask[0][2], (unsigned)bMask[0][3]);
    }
    __syncthreads();

    // ---- gate C (optional) ----
    if (ngates == 3) {
        unsigned baseC = 0;
#pragma unroll
        for (int j = 0; j < 8; j++)
            if ((tid >> j) & 1) baseC |= 1u << nbArr[1][j];
        apply_gate(S, sG[2], baseC, (unsigned)bMask[1][0], (unsigned)bMask[1][1],
                   (unsigned)bMask[1][2], (unsigned)bMask[1][3]);
        __syncthreads();
    }

    // ---- copy-out ----
    float* __restrict__ dstRe = dst;
    float* __restrict__ dstIm = dst + NSTATE;
#pragma unroll
    for (int cc = 0; cc < 16; cc++) {
        unsigned gHi = 0, sHi = 0;
#pragma unroll
        for (int jj = 0; jj < 4; jj++)
            if ((cc >> jj) & 1) {
                gHi |= 1u << pArr[8 + jj];
                sHi |= 1u << slotArr[8 + jj];
            }
        unsigned g = outer + gHi + gLo;
        float2 v = S[SADDR2(sHi + sLo)];
        dstRe[g] = v.x;
        dstIm[g] = v.y;
    }
}

extern "C" void kernel_launch(void* const* d_in, const int* in_sizes, int n_in,
                              void* d_out, int out_size) {
    const float* state   = (const float*)d_in[0];
    const int*   targets = (const int*)d_in[1];
    const float* gates   = (const float*)d_in[2];
    float*       out     = (float*)d_out;

    dim3 block(256);
    dim3 grid(NBLOCKS);

    qstep3_kernel<<<grid, block>>>(state, out, gates, targets, 0, 1, 2);
    qstep3_kernel<<<grid, block>>>(out, out, gates, targets, 3, 4, 5);
    qstep3_kernel<<<grid, block>>>(out, out, gates, targets, 6, 7, -1);
}

// round 5
// speedup vs baseline: 1.1363x; 1.0185x over previous
#include <cuda_runtime.h>
#include <cstdint>

// QuantumCircuitSimulator2: 24 qubits, 8 steps of 4-qubit (16x16 complex) gates.
// 3-step fusion in a 4096-amplitude SMEM tile (float2, skew a = s + (s>>4)).
// Gate-table reads via LDS.128 (the round-4 bottleneck), addresses via additive
// skewed K-constants, Karatsuba complex matvec on fma.rn.f32x2.

#define NQ 24
#define NSTATE (1u << NQ)
#define TILE_BITS 12
#define TILE (1u << TILE_BITS)
#define NBLOCKS (1u << (NQ - TILE_BITS))
#define PLANE (TILE + (TILE >> 4))     // 4352 float2

#define SADDR2(s) ((s) + ((s) >> 4))

typedef unsigned long long u64;

__device__ __forceinline__ u64 fma2(u64 a, u64 b, u64 c) {
    u64 d;
    asm("fma.rn.f32x2 %0, %1, %2, %3;" : "=l"(d) : "l"(a), "l"(b), "l"(c));
    return d;
}
__device__ __forceinline__ u64 add2(u64 a, u64 b) {
    u64 d;
    asm("add.rn.f32x2 %0, %1, %2;" : "=l"(d) : "l"(a), "l"(b));
    return d;
}
__device__ __forceinline__ u64 pack2(float lo, float hi) {
    u64 d;
    asm("mov.b64 %0, {%1, %2};" : "=l"(d) : "f"(lo), "f"(hi));
    return d;
}
__device__ __forceinline__ void unpack2(u64 v, float& lo, float& hi) {
    asm("mov.b64 {%0, %1}, %2;" : "=f"(lo), "=f"(hi) : "l"(v));
}

// One 16x16 complex gate on this thread's group.
// sG: Karatsuba tables (A=gr, B=gr+gi, C=gi-gr), 256 floats each.
// Addresses: skewed-additive, addr = aBase + sum of K_t for set gate bits.
__device__ __forceinline__ void apply_gate(float2* __restrict__ S,
                                           const float* __restrict__ sG,
                                           unsigned aBase, unsigned K0,
                                           unsigned K1, unsigned K2,
                                           unsigned K3) {
    u64 sr2[8], si2[8], u2[8];
#pragma unroll
    for (int kk = 0; kk < 8; kk++) {
        unsigned a0 = aBase + ((kk & 1) ? K1 : 0u) + ((kk & 2) ? K2 : 0u) +
                      ((kk & 4) ? K3 : 0u);
        float2 c0 = S[a0];
        float2 c1 = S[a0 + K0];
        sr2[kk] = pack2(c0.x, c1.x);
        si2[kk] = pack2(c0.y, c1.y);
        u2[kk]  = add2(sr2[kk], si2[kk]);
    }
    const u64 NEG1 = pack2(-1.0f, -1.0f);
#pragma unroll
    for (int j = 0; j < 16; j++) {
        const float4* A4 = reinterpret_cast<const float4*>(sG + j * 16);
        const float4* B4 = reinterpret_cast<const float4*>(sG + 256 + j * 16);
        const float4* C4 = reinterpret_cast<const float4*>(sG + 512 + j * 16);
        u64 a1 = 0ull, a2 = 0ull, a3 = 0ull;
#pragma unroll
        for (int q = 0; q < 4; q++) {
            float4 av = A4[q], bv = B4[q], cv = C4[q];
            a1 = fma2(pack2(av.x, av.y), u2[2 * q], a1);
            a2 = fma2(pack2(bv.x, bv.y), si2[2 * q], a2);
            a3 = fma2(pack2(cv.x, cv.y), sr2[2 * q], a3);
            a1 = fma2(pack2(av.z, av.w), u2[2 * q + 1], a1);
            a2 = fma2(pack2(bv.z, bv.w), si2[2 * q + 1], a2);
            a3 = fma2(pack2(cv.z, cv.w), sr2[2 * q + 1], a3);
        }
        u64 dre = fma2(a2, NEG1, a1);  // a1 - a2  -> re halves
        u64 dim = add2(a1, a3);        // a1 + a3  -> im halves
        float rl, rh, il, ih;
        unpack2(dre, rl, rh);
        unpack2(dim, il, ih);
        unsigned aj = aBase + ((j & 1) ? K0 : 0u) + ((j & 2) ? K1 : 0u) +
                      ((j & 4) ? K2 : 0u) + ((j & 8) ? K3 : 0u);
        S[aj] = make_float2(rl + rh, il + ih);
    }
}

__global__ __launch_bounds__(256, 3)
void qstep3_kernel(const float* __restrict__ src,
                   float* __restrict__ dst,
                   const float* __restrict__ gates,
                   const int* __restrict__ targets_raw,
                   int stepA, int stepB, int stepC) {
    __shared__ __align__(16) float2 S[PLANE];
    __shared__ __align__(16) float sG[3][768];
    __shared__ int pArr[12];        // physical bits of V (ascending)
    __shared__ int slotArr[12];     // SMEM slot of bit pArr[j]
    __shared__ int bK[2][4];        // skew-additive K of gate B/C target slots
    __shared__ int nbArr[2][8];     // non-target slots (ascending): B, C
    __shared__ unsigned uVmask;

    const int tid = threadIdx.x;
    const int ngates = (stepC >= 0) ? 3 : 2;

    // ---- Karatsuba gate tables ----
    {
        int steps[3] = {stepA, stepB, stepC};
        for (int g = 0; g < ngates; g++) {
            const float* gp = gates + (size_t)steps[g] * 512;
            for (int i = tid; i < 768; i += 256) {
                int t = i >> 8;
                int idx = i & 255;
                float gr = gp[idx], gi = gp[256 + idx];
                sG[g][i] = (t == 0) ? gr : ((t == 1) ? (gr + gi) : (gi - gr));
            }
        }
    }

    // ---- per-block setup ----
    if (tid == 0) {
        int stride = (targets_raw[1] == 0 && targets_raw[3] == 0) ? 2 : 1;
        int steps[3] = {stepA, stepB, stepC};
        int q[3][4];
        for (int g = 0; g < ngates; g++)
            for (int t = 0; t < 4; t++)
                q[g][t] = targets_raw[(steps[g] * 4 + t) * stride];

        unsigned U = 0;
        for (int g = 0; g < ngates; g++)
            for (int t = 0; t < 4; t++) U |= 1u << q[g][t];
        unsigned V = U;
        int need = TILE_BITS - __popc(U);
        for (int b = 0; need > 0; b++)
            if (!((V >> b) & 1u)) { V |= 1u << b; need--; }
        uVmask = V;

        int slot_of[24];
        for (int b = 0; b < 24; b++) slot_of[b] = -1;
        for (int t = 0; t < 4; t++) slot_of[q[0][t]] = 8 + t;  // A: slots 8..11
        int hi = 7;
        for (int g = 1; g < ngates; g++)
            for (int t = 0; t < 4; t++)
                if (slot_of[q[g][t]] < 0) slot_of[q[g][t]] = hi--;
        int fs = 0;
        for (int b = 0; b < 24; b++)
            if (((V >> b) & 1u) && slot_of[b] < 0) slot_of[b] = fs++;

        int j = 0;
        for (int b = 0; b < 24; b++)
            if ((V >> b) & 1u) { pArr[j] = b; slotArr[j] = slot_of[b]; j++; }

        for (int g = 1; g < ngates; g++) {
            unsigned tm = 0;
            for (int t = 0; t < 4; t++) {
                unsigned m = 1u << slot_of[q[g][t]];
                bK[g - 1][t] = (int)(m + (m >> 4));  // skew-additive K
                tm |= m;
            }
            int jj = 0;
            for (int s3 = 0; s3 < 12; s3++)
                if (!((tm >> s3) & 1u)) nbArr[g - 1][jj++] = s3;
        }
    }
    __syncthreads();

    // ---- per-thread mappings ----
    const unsigned V = uVmask;
    unsigned outer = 0;
    {
        unsigned ob = blockIdx.x;
        for (int b = 0; b < 24; b++)
            if (!((V >> b) & 1u)) { outer |= (ob & 1u) << b; ob >>= 1; }
    }
    unsigned gLo = 0, sLo = 0;
#pragma unroll
    for (int j = 0; j < 8; j++)
        if ((tid >> j) & 1) { gLo |= 1u << pArr[j]; sLo |= 1u << slotArr[j]; }

    const float* __restrict__ srcRe = src;
    const float* __restrict__ srcIm = src + NSTATE;

    // ---- copy-in: coalesced global -> permuted SMEM (float2) ----
#pragma unroll
    for (int cc = 0; cc < 16; cc++) {
        unsigned gHi = 0, sHi = 0;
#pragma unroll
        for (int jj = 0; jj < 4; jj++)
            if ((cc >> jj) & 1) {
                gHi |= 1u << pArr[8 + jj];
                sHi |= 1u << slotArr[8 + jj];
            }
        unsigned g = outer + gHi + gLo;
        S[SADDR2(sHi + sLo)] = make_float2(srcRe[g], srcIm[g]);
    }
    __syncthreads();

    // ---- gate A: targets at slots 8..11 (gate order), base = tid ----
    // K(m) = m + (m>>4): 256->272, 512->544, 1024->1088, 2048->2176
    apply_gate(S, sG[0], SADDR2((unsigned)tid), 272u, 544u, 1088u, 2176u);
    __syncthreads();

    // ---- gate B ----
    {
        unsigned baseB = 0;
#pragma unroll
        for (int j = 0; j < 8; j++)
            if ((tid >> j) & 1) baseB |= 1u << nbArr[0][j];
        apply_gate(S, sG[1], SADDR2(baseB), (unsigned)bK[0][0],
                   (unsigned)bK[0][1], (unsigned)bK[0][2], (unsigned)bK[0][3]);
    }
    __syncthreads();

    // ---- gate C (optional) ----
    if (ngates == 3) {
        unsigned baseC = 0;
#pragma unroll
        for (int j = 0; j < 8; j++)
            if ((tid >> j) & 1) baseC |= 1u << nbArr[1][j];
        apply_gate(S, sG[2], SADDR2(baseC), (unsigned)bK[1][0],
                   (unsigned)bK[1][1], (unsigned)bK[1][2], (unsigned)bK[1][3]);
        __syncthreads();
    }

    // ---- copy-out ----
    float* __restrict__ dstRe = dst;
    float* __restrict__ dstIm = dst + NSTATE;
#pragma unroll
    for (int cc = 0; cc < 16; cc++) {
        unsigned gHi = 0, sHi = 0;
#pragma unroll
        for (int jj = 0; jj < 4; jj++)
            if ((cc >> jj) & 1) {
                gHi |= 1u << pArr[8 + jj];
                sHi |= 1u << slotArr[8 + jj];
            }
        unsigned g = outer + gHi + gLo;
        float2 v = S[SADDR2(sHi + sLo)];
        dstRe[g] = v.x;
        dstIm[g] = v.y;
    }
}

extern "C" void kernel_launch(void* const* d_in, const int* in_sizes, int n_in,
                              void* d_out, int out_size) {
    const float* state   = (const float*)d_in[0];
    const int*   targets = (const int*)d_in[1];
    const float* gates   = (const float*)d_in[2];
    float*       out     = (float*)d_out;

    dim3 block(256);
    dim3 grid(NBLOCKS);

    qstep3_kernel<<<grid, block>>>(state, out, gates, targets, 0, 1, 2);
    qstep3_kernel<<<grid, block>>>(out, out, gates, targets, 3, 4, 5);
    qstep3_kernel<<<grid, block>>>(out, out, gates, targets, 6, 7, -1);
}